// round 17
// baseline (speedup 1.0000x reference)
#include <cuda_runtime.h>
#include <cstdint>

// ---------------------------------------------------------------------------
// NeuralSDEHead: batch=8, d_model=512, hidden=64, n_paths=4096, horizon=128
// out = [paths (8*4096*128), mu (8), sigma (8)]  all fp32
// PRNG: JAX threefry2x32, jax_threefry_partitionable=True semantics.
//
// Pipeline:
//  (1) setup_kernel: per-batch bases + mu/sigma (65 blocks)
//  (2) build_table_kernel: f/g over two-tier y-grid (64 pts per (b,step))
//  (3) path_kernel: whole batch table (64 KB) staged in smem once; inline
//      one-step-ahead threefry noise; branch-free clamped LDS cubic loop.
// ---------------------------------------------------------------------------

#define BATCH    8
#define DMODEL   512
#define HIDDEN   64
#define NPATHS   4096
#define HORIZON  128
#define BN       (BATCH * NPATHS)      /* 32768 */
#define PATHS_ELEMS (BN * HORIZON)     /* 4194304 */

#define GI       32                     /* inner grid points (d=2)  */
#define GO       32                     /* outer grid points (d=12) */
#define TAB_G    (GI + GO)              /* 64 per (b,step) slice */
#define SLICE_B  (TAB_G * 8)            /* 512 bytes */
#define TAB_SMEM (HORIZON * SLICE_B)    /* 65536 bytes = 64 KB */
#define YI_MIN   (-32.0f)
#define YI_D     (2.0f)
#define YI_INV   (0.5f)
#define YO_MIN   (-192.0f)
#define YO_D     (12.0f)
#define YO_INV   (1.0f / 12.0f)

typedef unsigned long long ull;

// Scratch (allocation-free rule: __device__ globals)
__device__ float        g_base_f1[BATCH * HIDDEN];
__device__ float        g_base_g1[BATCH * HIDDEN];
__device__ __align__(16) float2 g_tab[BATCH * HORIZON * TAB_G];  // 512 KB

// ---------------------------------------------------------------------------
// Threefry-2x32 (JAX-compatible, 20 rounds)
// ---------------------------------------------------------------------------
__device__ __forceinline__ void threefry2x32(unsigned int k0, unsigned int k1,
                                             unsigned int x0, unsigned int x1,
                                             unsigned int* o0, unsigned int* o1)
{
    unsigned int ks0 = k0, ks1 = k1, ks2 = k0 ^ k1 ^ 0x1BD11BDAu;
    x0 += ks0; x1 += ks1;
#define TF_ROUND(r) { x0 += x1; x1 = __funnelshift_l(x1, x1, (r)); x1 ^= x0; }
    TF_ROUND(13) TF_ROUND(15) TF_ROUND(26) TF_ROUND(6)
    x0 += ks1; x1 += ks2 + 1u;
    TF_ROUND(17) TF_ROUND(29) TF_ROUND(16) TF_ROUND(24)
    x0 += ks2; x1 += ks0 + 2u;
    TF_ROUND(13) TF_ROUND(15) TF_ROUND(26) TF_ROUND(6)
    x0 += ks0; x1 += ks1 + 3u;
    TF_ROUND(17) TF_ROUND(29) TF_ROUND(16) TF_ROUND(24)
    x0 += ks1; x1 += ks2 + 4u;
    TF_ROUND(13) TF_ROUND(15) TF_ROUND(26) TF_ROUND(6)
    x0 += ks2; x1 += ks0 + 5u;
#undef TF_ROUND
    *o0 = x0; *o1 = x1;
}

// XLA ErfInv32 (Giles polynomial)
__device__ __forceinline__ float erfinv_xla(float x)
{
    float w = -log1pf(-x * x);
    float p;
    if (w < 5.0f) {
        w = w - 2.5f;
        p = 2.81022636e-08f;
        p = fmaf(p, w, 3.43273939e-07f);
        p = fmaf(p, w, -3.5233877e-06f);
        p = fmaf(p, w, -4.39150654e-06f);
        p = fmaf(p, w, 0.00021858087f);
        p = fmaf(p, w, -0.00125372503f);
        p = fmaf(p, w, -0.00417768164f);
        p = fmaf(p, w, 0.246640727f);
        p = fmaf(p, w, 1.50140941f);
    } else {
        w = sqrtf(w) - 3.0f;
        p = -0.000200214257f;
        p = fmaf(p, w, 0.000100950558f);
        p = fmaf(p, w, 0.00134934322f);
        p = fmaf(p, w, -0.00367342844f);
        p = fmaf(p, w, 0.00573950773f);
        p = fmaf(p, w, -0.0076224613f);
        p = fmaf(p, w, 0.00943887047f);
        p = fmaf(p, w, 1.00167406f);
        p = fmaf(p, w, 2.83297682f);
    }
    return p * x;
}

__device__ __forceinline__ float silu_f(float x)
{
    return __fdividef(x, 1.0f + __expf(-x));
}

__device__ __forceinline__ float softplus_acc(float x)
{
    return fmaxf(x, 0.0f) + log1pf(__expf(-fabsf(x)));
}

// packed f32x2 helpers -------------------------------------------------------
__device__ __forceinline__ ull pack_dup(float x)
{
    unsigned int b = __float_as_uint(x);
    ull r;
    asm("mov.b64 %0, {%1, %2};" : "=l"(r) : "r"(b), "r"(b));
    return r;
}
__device__ __forceinline__ ull pack2(float lo, float hi)
{
    unsigned int a = __float_as_uint(lo), b = __float_as_uint(hi);
    ull r;
    asm("mov.b64 %0, {%1, %2};" : "=l"(r) : "r"(a), "r"(b));
    return r;
}
__device__ __forceinline__ float2 unpack2(ull v)
{
    unsigned int lo, hi;
    asm("mov.b64 {%0, %1}, %2;" : "=r"(lo), "=r"(hi) : "l"(v));
    return make_float2(__uint_as_float(lo), __uint_as_float(hi));
}
#define FMA2(acc, a, b) asm("fma.rn.f32x2 %0, %1, %2, %0;" : "+l"(acc) : "l"(a), "l"(b))

__device__ __forceinline__ unsigned int smem_u32(const void* p)
{
    unsigned int a;
    asm("{ .reg .u64 t; cvta.to.shared.u64 t, %1; cvt.u32.u64 %0, t; }"
        : "=r"(a) : "l"(p));
    return a;
}

// grid point for table index 0..63: inner 0..31, outer 32..63
__device__ __forceinline__ float y_of_idx(int idx)
{
    return (idx < GI) ? (YI_MIN + (float)idx * YI_D)
                      : (YO_MIN + (float)(idx - GI) * YO_D);
}

// ---------------------------------------------------------------------------
// Setup kernel: 65 blocks x 256 threads.
//  blocks [0, 64): per-batch bases (16 threads per column, 16 cols/block)
//  block 64: mu/sigma (warp w = batch w)
// ---------------------------------------------------------------------------
__global__ __launch_bounds__(256)
void setup_kernel(const float* __restrict__ h_t,
                  const float* __restrict__ W_f1, const float* __restrict__ b_f1,
                  const float* __restrict__ W_g1, const float* __restrict__ b_g1,
                  const float* __restrict__ W_mu, const float* __restrict__ b_mu,
                  const float* __restrict__ W_sig, const float* __restrict__ b_sig,
                  float* __restrict__ out_mu, float* __restrict__ out_sigma)
{
    const int n   = blockIdx.x;
    const int tid = threadIdx.x;

    if (n < 64) {
        // ---- bases: 16 threads/column, 16 columns per block ----
        const int b    = n >> 3;               // batch (8 blocks per batch)
        const int part = n & 7;                // 0-3: f cols; 4-7: g cols
        const float* h = h_t + b * DMODEL;
        const int col  = ((part & 3) * 16) + (tid >> 4);   // 0..63
        const int q    = tid & 15;
        const int i0   = q * 32;
        if (part < 4) {
            float s = 0.0f;
            #pragma unroll 8
            for (int i = i0; i < i0 + 32; ++i)
                s = fmaf(h[i], W_f1[i * HIDDEN + col], s);
            s += __shfl_xor_sync(0xffffffffu, s, 1);
            s += __shfl_xor_sync(0xffffffffu, s, 2);
            s += __shfl_xor_sync(0xffffffffu, s, 4);
            s += __shfl_xor_sync(0xffffffffu, s, 8);
            if (q == 0) g_base_f1[b * HIDDEN + col] = s + b_f1[col];
        } else {
            float s = 0.0f;
            #pragma unroll 8
            for (int i = i0; i < i0 + 32; ++i)
                s = fmaf(h[i], W_g1[i * HIDDEN + col], s);
            s += __shfl_xor_sync(0xffffffffu, s, 1);
            s += __shfl_xor_sync(0xffffffffu, s, 2);
            s += __shfl_xor_sync(0xffffffffu, s, 4);
            s += __shfl_xor_sync(0xffffffffu, s, 8);
            if (q == 0) g_base_g1[b * HIDDEN + col] = s + b_g1[col];
        }
    } else {
        // ---- mu/sigma: warp w = batch w ----
        const int w    = tid >> 5;             // 0..7
        const int lane = tid & 31;
        const float* h = h_t + w * DMODEL;
        float sm = 0.0f, ss = 0.0f;
        #pragma unroll 4
        for (int i = lane; i < DMODEL; i += 32) {
            float hv = h[i];
            sm = fmaf(hv, W_mu[i], sm);
            ss = fmaf(hv, W_sig[i], ss);
        }
        #pragma unroll
        for (int off = 16; off > 0; off >>= 1) {
            sm += __shfl_xor_sync(0xffffffffu, sm, off);
            ss += __shfl_xor_sync(0xffffffffu, ss, off);
        }
        if (lane == 0) {
            out_mu[w] = sm + b_mu[0];
            float v = ss + b_sig[0];
            out_sigma[w] = fmaxf(v, 0.0f) + log1pf(expf(-fabsf(v))) + 1e-6f;
        }
    }
}

// ---------------------------------------------------------------------------
// Table build kernel: 1024 blocks (one per (b, step)) x 64 threads.
// One eval per thread (64 grid points). occ 8 -> single wave chip-wide.
// ---------------------------------------------------------------------------
__global__ __launch_bounds__(64, 8)
void build_table_kernel(const float* __restrict__ W_f1,
                        const float* __restrict__ W_f2, const float* __restrict__ b_f2,
                        const float* __restrict__ W_f3, const float* __restrict__ b_f3,
                        const float* __restrict__ W_g1,
                        const float* __restrict__ W_g2, const float* __restrict__ b_g2)
{
    __shared__ __align__(16) float sWf2[HIDDEN * HIDDEN];   // 16 KB
    __shared__ __align__(16) float sbf2[HIDDEN];
    __shared__ __align__(16) float4 sP[HIDDEN];  // {tbase_f, wy_f, tbase_g, wy_g}
    __shared__ float sWf3[HIDDEN], sWg2[HIDDEN];

    const int tid  = threadIdx.x;           // 0..63
    const int b    = blockIdx.x >> 7;       // 0..7
    const int step = blockIdx.x & 127;      // 0..127
    const float t  = (float)step;

    for (int i = tid; i < HIDDEN * HIDDEN; i += 64) sWf2[i] = W_f2[i];
    {
        sbf2[tid] = b_f2[tid];
        sWf3[tid] = W_f3[tid];
        sWg2[tid] = W_g2[tid];
        sP[tid] = make_float4(
            fmaf(t, W_f1[513 * HIDDEN + tid], g_base_f1[b * HIDDEN + tid]),
            W_f1[512 * HIDDEN + tid],
            fmaf(t, W_g1[513 * HIDDEN + tid], g_base_g1[b * HIDDEN + tid]),
            W_g1[512 * HIDDEN + tid]);
    }
    __syncthreads();

    const float bf3v = b_f3[0];
    const float bg2v = b_g2[0];
    float2* slice = g_tab + (size_t)(b * HORIZON + step) * TAB_G;

    const float y = y_of_idx(tid);

    ull acc[HIDDEN / 2];
    #pragma unroll
    for (int m = 0; m < HIDDEN / 2; ++m)
        acc[m] = pack2(sbf2[2 * m], sbf2[2 * m + 1]);
    float ga0 = bg2v, ga1 = 0.0f;

    #pragma unroll 4
    for (int i = 0; i < HIDDEN; ++i) {
        const float4 p4 = sP[i];
        const float hf = silu_f(fmaf(y, p4.y, p4.x));
        const float hg = silu_f(fmaf(y, p4.w, p4.z));
        const float gw = sWg2[i];
        if ((i & 1) == 0) ga0 = fmaf(hg, gw, ga0);
        else              ga1 = fmaf(hg, gw, ga1);

        const ull a2 = pack_dup(hf);
        const ulonglong2* wr = reinterpret_cast<const ulonglong2*>(&sWf2[i * HIDDEN]);
        #pragma unroll
        for (int q = 0; q < HIDDEN / 4; ++q) {
            ulonglong2 w = wr[q];
            FMA2(acc[2 * q],     a2, w.x);
            FMA2(acc[2 * q + 1], a2, w.y);
        }
    }

    float f0 = bf3v, f1 = 0.0f;
    #pragma unroll
    for (int m = 0; m < HIDDEN / 2; ++m) {
        float2 h2 = unpack2(acc[m]);
        f0 = fmaf(silu_f(h2.x), sWf3[2 * m],     f0);
        f1 = fmaf(silu_f(h2.y), sWf3[2 * m + 1], f1);
    }
    slice[tid] = make_float2(f0 + f1, softplus_acc(ga0 + ga1) + 1e-6f);
}

// ---------------------------------------------------------------------------
// Path kernel: 256 blocks x 128 threads, 1 path per thread. Whole batch
// table (64 KB) staged via cp.async once. Inline one-step-ahead threefry
// noise. Branch-free, call-free clamped two-tier cubic lookup:
//   beyond the outer grid edge, indices clamp (f,g are silu-saturated
//   constants out there and outputs clamp to exp(+-20) regardless).
// ---------------------------------------------------------------------------
extern __shared__ __align__(16) float2 stab[];   // HORIZON * TAB_G entries

__global__ __launch_bounds__(128)
void path_kernel(const float* __restrict__ initial_price,
                 float* __restrict__ out_paths)
{
    __shared__ unsigned int skeys[2 * HORIZON];

    const int tid = threadIdx.x;                  // 0..127
    const int bid = blockIdx.x;                   // 0..255
    const int row = bid * 128 + tid;
    const int b   = row >> 12;                    // uniform per block

    // split keys: key[j] = threefry((0,42), (0,j)) — one per thread
    {
        unsigned int o0, o1;
        threefry2x32(0u, 42u, 0u, (unsigned int)tid, &o0, &o1);
        skeys[2 * tid]     = o0;
        skeys[2 * tid + 1] = o1;
    }

    // stage the whole batch table (64 KB) via cp.async
    {
        const char* src = (const char*)(g_tab + (size_t)b * HORIZON * TAB_G);
        const unsigned int dst = smem_u32(stab);
        #pragma unroll
        for (int k = 0; k < TAB_SMEM / (128 * 16); ++k) {   // 32 iters
            const int off = (k * 128 + tid) * 16;
            asm volatile("cp.async.cg.shared.global [%0], [%1], 16;"
                         :: "r"(dst + off), "l"(src + off));
        }
        asm volatile("cp.async.commit_group;");
    }

    float y = logf(initial_price[b]);
    float4* outp4 = reinterpret_cast<float4*>(out_paths + (size_t)row * HORIZON);
    const unsigned int cnt = (unsigned int)row;

    asm volatile("cp.async.wait_group 0;");
    __syncthreads();   // table + keys visible

    // inline noise: z(s) from skeys — independent of y
    #define ZGEN(s, zout) do {                                                \
        unsigned int _o0, _o1;                                                \
        threefry2x32(skeys[2 * (s)], skeys[2 * (s) + 1], 0u, cnt, &_o0, &_o1);\
        const unsigned int _bits = _o0 ^ _o1;                                 \
        const float _u01 = __uint_as_float((_bits >> 9) | 0x3f800000u) - 1.0f;\
        float _u = fmaf(_u01, 2.0f, -0.99999994039535522f);                   \
        _u = fmaxf(-0.99999994039535522f, _u);                                \
        (zout) = 1.4142135381698608f * erfinv_xla(_u);                        \
    } while (0)

    float z_next;
    ZGEN(0, z_next);

    #pragma unroll 1
    for (int g = 0; g < HORIZON / 4; ++g) {
        float o[4];
        #pragma unroll
        for (int k = 0; k < 4; ++k) {
            const int s = g * 4 + k;
            const float z = z_next;
            if (s + 1 < HORIZON) ZGEN(s + 1, z_next);  // overlaps lookup below

            const float2* cur = stab + s * TAB_G;

            // ---- clamped two-tier cubic lookup (branch-free paths) ----
            float p  = (y - YI_MIN) * YI_INV;
            int  i1  = (int)floorf(p);
            const bool inner = (i1 >= 1) && (i1 <= GI - 3);
            if (!inner) {
                p  = (y - YO_MIN) * YO_INV;
                i1 = (int)floorf(p);
                i1 = max(1, min(GO - 3, i1));          // clamp to outer edge
            }
            float uu = p - (float)i1;
            uu = fminf(fmaxf(uu, 0.0f), 1.0f);          // clamp frac on edges
            const int off = inner ? i1 : (GI + i1);

            const float2 q0 = cur[off - 1];
            const float2 q1 = cur[off];
            const float2 q2 = cur[off + 1];
            const float2 q3 = cur[off + 2];
            const float u2 = uu * uu;
            const float u3 = u2 * uu;
            const float w0 = 0.5f * (-u3 + 2.0f * u2 - uu);
            const float w1 = 0.5f * (3.0f * u3 - 5.0f * u2 + 2.0f);
            const float w2 = 0.5f * (-3.0f * u3 + 4.0f * u2 + uu);
            const float w3 = 0.5f * (u3 - u2);
            const float f  = w0 * q0.x + w1 * q1.x + w2 * q2.x + w3 * q3.x;
            const float gg = w0 * q0.y + w1 * q1.y + w2 * q2.y + w3 * q3.y;

            // Euler-Maruyama (dt = 1, sqrt_dt = 1)
            y = (y + f) + gg * z;
            o[k] = __expf(fminf(fmaxf(y, -20.0f), 20.0f));
        }
        outp4[g] = make_float4(o[0], o[1], o[2], o[3]);
    }
    #undef ZGEN
}

// ---------------------------------------------------------------------------
// Launch (graph-capturable: kernels only, no allocs/syncs) — 3 launches.
// ---------------------------------------------------------------------------
extern "C" void kernel_launch(void* const* d_in, const int* in_sizes, int n_in,
                              void* d_out, int out_size)
{
    const float* h_t    = (const float*)d_in[0];
    const float* price  = (const float*)d_in[1];
    const float* W_f1   = (const float*)d_in[2];
    const float* b_f1   = (const float*)d_in[3];
    const float* W_f2   = (const float*)d_in[4];
    const float* b_f2   = (const float*)d_in[5];
    const float* W_f3   = (const float*)d_in[6];
    const float* b_f3   = (const float*)d_in[7];
    const float* W_g1   = (const float*)d_in[8];
    const float* b_g1   = (const float*)d_in[9];
    const float* W_g2   = (const float*)d_in[10];
    const float* b_g2   = (const float*)d_in[11];
    const float* W_mu   = (const float*)d_in[12];
    const float* b_mu   = (const float*)d_in[13];
    const float* W_sig  = (const float*)d_in[14];
    const float* b_sig  = (const float*)d_in[15];

    float* out        = (float*)d_out;
    float* out_paths  = out;
    float* out_mu     = out + PATHS_ELEMS;
    float* out_sigma  = out + PATHS_ELEMS + BATCH;

    // opt-in to 64 KB dynamic smem for the path kernel (idempotent)
    cudaFuncSetAttribute(path_kernel,
                         cudaFuncAttributeMaxDynamicSharedMemorySize, TAB_SMEM);

    setup_kernel<<<65, 256>>>(h_t, W_f1, b_f1, W_g1, b_g1,
                              W_mu, b_mu, W_sig, b_sig,
                              out_mu, out_sigma);
    build_table_kernel<<<BATCH * HORIZON, 64>>>(W_f1, W_f2, b_f2, W_f3, b_f3,
                                                W_g1, W_g2, b_g2);
    path_kernel<<<256, 128, TAB_SMEM>>>(price, out_paths);
}